// round 5
// baseline (speedup 1.0000x reference)
#include <cuda_runtime.h>
#include <cuda_bf16.h>

// Fixed problem shapes
#define BV 4
#define DV 48
#define HV 32
#define WV 88
#define CV 64
#define NXV 200
#define NYV 200
#define HWV (HV * WV)
#define NPRIME (BV * DV * HV * WV)       // 540672 points (divisible by 32)
#define NXY (NXV * NYV)                  // 40000
#define NGROUP (CV / 4)                  // 16 four-channel groups
#define NGTOT (BV * NGROUP * NXY)        // 2,560,000 groups
#define SCRATCH_ELEMS (NGTOT * 4)        // 10,240,000 floats = 41 MB
#define NXY4 (NXY / 4)                   // 10000 quads per (b,c4) plane
#define NQUAD (NGTOT / 4)                // 640,000 transpose quads

// Channel-interleaved accumulator: [b][c4][nxy][4] -> 16B-contiguous groups so
// one point's contribution to 4 channels is a single red.global.add.v4.f32.
__device__ float g_scratch[SCRATCH_ELEMS];

// One-wave grid-stride zero with 4x float4 ILP per iteration.
__global__ void zero_scratch_kernel() {
    float4* p = reinterpret_cast<float4*>(g_scratch);
    const int n4 = SCRATCH_ELEMS / 4;                 // 2,560,000
    const int stride = gridDim.x * blockDim.x;
    const float4 z = make_float4(0.f, 0.f, 0.f, 0.f);
    for (int i = blockIdx.x * blockDim.x + threadIdx.x; i < n4; i += 4 * stride) {
        p[i] = z;
        if (i + stride     < n4) p[i + stride]     = z;
        if (i + 2 * stride < n4) p[i + 2 * stride] = z;
        if (i + 3 * stride < n4) p[i + 3 * stride] = z;
    }
}

__global__ void bev_scatter_kernel(const float* __restrict__ x,
                                   const float* __restrict__ geom,
                                   const float* __restrict__ mask,
                                   const float* __restrict__ dxp,
                                   const float* __restrict__ bxp) {
    const int lane = threadIdx.x & 31;
    const int warp = (blockIdx.x * blockDim.x + threadIdx.x) >> 5;
    const int nw   = (gridDim.x * blockDim.x) >> 5;

    const float dx0 = dxp[0], dx1 = dxp[1], dx2 = dxp[2];
    const float b0 = bxp[0] - 0.5f * dx0;
    const float b1 = bxp[1] - 0.5f * dx1;
    const float b2 = bxp[2] - 0.5f * dx2;

    const int half = lane >> 4;          // which of the 2 points this iteration
    const int sl   = lane & 15;          // 4-channel group within the point

    for (int p0 = warp * 32; p0 < NPRIME; p0 += nw * 32) {
        // ---- phase 1: all 32 lanes compute one point's voxel base each ----
        const int p = p0 + lane;
        // IEEE fp32 div + truncation toward zero matches reference astype(int32)
        const float gx = (geom[p * 3 + 0] - b0) / dx0;
        const float gy = (geom[p * 3 + 1] - b1) / dx1;
        const float gz = (geom[p * 3 + 2] - b2) / dx2;
        const int ix = (int)gx;
        const int iy = (int)gy;
        const int iz = (int)gz;

        const int hw = p % HWV;
        const int bn = p / (DV * HWV);   // batch index (N=1)

        int base = -1;
        if ((ix >= 0) & (ix < NXV) &
            (iy >= 0) & (iy < NYV) &
            (iz >= 0) & (iz < 1) &
            (mask[(bn * 2 + 1) * HWV + hw] > 0.5f)) {
            base = bn * (NGROUP * NXY) + ix * NYV + iy;
        }

        // ---- phase 2: 16 iterations, 2 points each (lanes 0-15 / 16-31) ----
        #pragma unroll
        for (int j = 0; j < 32; j += 2) {
            const int bj = __shfl_sync(0xffffffffu, base, j + half);
            if (bj >= 0) {
                const float4 v = *reinterpret_cast<const float4*>(
                    x + (size_t)(p0 + j + half) * CV + sl * 4);
                float* dst = g_scratch + (size_t)(bj + sl * NXY) * 4;
                asm volatile(
                    "red.global.add.v4.f32 [%0], {%1, %2, %3, %4};"
                    :: "l"(dst), "f"(v.x), "f"(v.y), "f"(v.z), "f"(v.w)
                    : "memory");
            }
        }
    }
}

// Interleaved scratch -> planar output via 4x4 register transpose.
// Each thread: 4 consecutive groups (64B contiguous scratch read), then one
// float4 store per channel plane (fully coalesced 512B/warp per plane).
__global__ void bev_unpack_kernel(float* __restrict__ out) {
    const int q = blockIdx.x * blockDim.x + threadIdx.x;
    if (q >= NQUAD) return;
    const int i  = q % NXY4;             // quad index along nxy
    const int t  = q / NXY4;             // (b, c4) plane: t in [0, 64)
    const int c4 = t & (NGROUP - 1);
    const int b  = t >> 4;

    const float4* sp = reinterpret_cast<const float4*>(g_scratch)
                       + (size_t)t * NXY + 4 * i;
    const float4 v0 = sp[0];
    const float4 v1 = sp[1];
    const float4 v2 = sp[2];
    const float4 v3 = sp[3];

    float* o = out + (size_t)(b * CV + c4 * 4) * NXY + 4 * i;
    *reinterpret_cast<float4*>(o + 0 * NXY) = make_float4(v0.x, v1.x, v2.x, v3.x);
    *reinterpret_cast<float4*>(o + 1 * NXY) = make_float4(v0.y, v1.y, v2.y, v3.y);
    *reinterpret_cast<float4*>(o + 2 * NXY) = make_float4(v0.z, v1.z, v2.z, v3.z);
    *reinterpret_cast<float4*>(o + 3 * NXY) = make_float4(v0.w, v1.w, v2.w, v3.w);
}

extern "C" void kernel_launch(void* const* d_in, const int* in_sizes, int n_in,
                              void* d_out, int out_size) {
    const float* x    = (const float*)d_in[0];
    const float* geom = (const float*)d_in[1];
    const float* mask = (const float*)d_in[2];
    const float* dx   = (const float*)d_in[3];
    const float* bx   = (const float*)d_in[4];
    float* out = (float*)d_out;

    // 1) zero the interleaved accumulator (41 MB), one-wave grid-stride
    zero_scratch_kernel<<<148 * 8, 256>>>();

    // 2) masked scatter with v4 reductions; batched warp-parallel indexing
    bev_scatter_kernel<<<1056, 256>>>(x, geom, mask, dx, bx);

    // 3) interleaved -> planar unpack, 4x4 register transpose, float4 stores
    bev_unpack_kernel<<<(NQUAD + 255) / 256, 256>>>(out);
}